// round 5
// baseline (speedup 1.0000x reference)
#include <cuda_runtime.h>
#include <math.h>

// ---------------------------------------------------------------------------
// DE3 fused: 256-bin histogram entropy, single kernel.
//   out = B * (8 + sum_i p_i log2 p_i),  p_i = counts[i] / (2048*2048)
//
// R4's explicit prefetch pipeline (proven: dur == bytes/DRAM-rate)
// + R3's conflict-free per-thread u8 bank-exclusive smem histograms
//   (bank == lane for every access; 256 B/thread -> 32 KB/block
//    -> 7 blocks/SM = 28 warps/SM).
//
//   counter(thread, bin) at byte  warp*8192 + (bin>>2)*128 + lane*4 + (bin&3)
//                               = bin*32 + base - (bin&3)*31
// Grid 3108 = 148*7*3 (3 waves). Max 43 float4/thread -> max count 172 < 255.
// ---------------------------------------------------------------------------

#define NUM_BINS 256
#define THREADS  128
#define BLOCKS   3108
#define SMEM_BYTES 32768      // 4 warps * 8192 B
#define DEPTH    4

__device__ unsigned int g_counts[NUM_BINS];   // zero-init at load
__device__ unsigned int g_done;

__global__ void __launch_bounds__(THREADS, 7)
de3_fused(const float4* __restrict__ in4, int n4,
          const float* __restrict__ in, int n,
          float* __restrict__ out)
{
    extern __shared__ unsigned char smem[];

    // zero private histograms: 2048 uint4 / 128 threads = 16 STS.128 each
    {
        uint4* z = reinterpret_cast<uint4*>(smem);
        #pragma unroll
        for (int i = threadIdx.x; i < SMEM_BYTES / 16; i += THREADS)
            z[i] = make_uint4(0u, 0u, 0u, 0u);
    }
    __syncthreads();

    const unsigned lane = threadIdx.x & 31u;
    const unsigned warp = threadIdx.x >> 5;
    const unsigned base = (warp << 13) + (lane << 2);   // warp*8192 + lane*4

    // bump: FMNMX, F2I, AND, IMAD, IMAD, LDS.U8, IADD, STS.U8 — conflict-free
    #define DE3_BUMP(V) do {                                           \
        unsigned b_  = __float2uint_rz(fminf((V), 255.0f));            \
        unsigned lo_ = b_ & 3u;                                        \
        unsigned a_  = b_ * 32u + base - lo_ * 31u;                    \
        smem[a_] = (unsigned char)(smem[a_] + 1u);                     \
    } while (0)
    #define DE3_BUMP4(Q) do { DE3_BUMP((Q).x); DE3_BUMP((Q).y);       \
                              DE3_BUMP((Q).z); DE3_BUMP((Q).w); } while (0)

    const int S  = BLOCKS * THREADS;     // 397824
    const int SD = DEPTH * S;
    int i = blockIdx.x * THREADS + threadIdx.x;

    // ---- DEPTH-deep software pipeline: next batch's LDG.128s issue BEFORE
    //      the current batch's smem work.
    if (i + (DEPTH - 1) * S < n4) {
        float4 buf[DEPTH];
        #pragma unroll
        for (int k = 0; k < DEPTH; ++k) buf[k] = __ldcs(in4 + i + k * S);
        i += SD;
        while (i + (DEPTH - 1) * S < n4) {
            float4 nxt[DEPTH];
            #pragma unroll
            for (int k = 0; k < DEPTH; ++k) nxt[k] = __ldcs(in4 + i + k * S);
            #pragma unroll
            for (int k = 0; k < DEPTH; ++k) DE3_BUMP4(buf[k]);
            #pragma unroll
            for (int k = 0; k < DEPTH; ++k) buf[k] = nxt[k];
            i += SD;
        }
        #pragma unroll
        for (int k = 0; k < DEPTH; ++k) DE3_BUMP4(buf[k]);
    }
    for (; i < n4; i += S) {
        float4 a = __ldcs(in4 + i);
        DE3_BUMP4(a);
    }
    if (blockIdx.x == 0 && (int)threadIdx.x < (n & 3)) {
        float v = in[(n & ~3) + (int)threadIdx.x];
        DE3_BUMP(v);
    }
    #undef DE3_BUMP4
    #undef DE3_BUMP
    __syncthreads();

    // ---- block reduction (proven in R3) -----------------------------------
    // Word (warp w, row r, lane l) at word-index w*2048 + r*32 + l holds the
    // u8 counters of bins 4r..4r+3 for thread (w,l). dp4a byte-lane sums.
    {
        const unsigned* w32 = reinterpret_cast<const unsigned*>(smem);
        const unsigned j = threadIdx.x;
        const unsigned r = j & 63u;
        const unsigned wp0 = (j >> 6) << 1;
        unsigned s0 = 0u, s1 = 0u, s2 = 0u, s3 = 0u;
        #pragma unroll
        for (unsigned w = 0; w < 2; ++w) {
            const unsigned rowbase = (wp0 + w) * 2048u + r * 32u;
            #pragma unroll
            for (unsigned k = 0; k < 32; ++k) {
                unsigned l = (k + j) & 31u;
                unsigned wd = w32[rowbase + l];
                s0 = __dp4a(wd, 0x00000001u, s0);
                s1 = __dp4a(wd, 0x00000100u, s1);
                s2 = __dp4a(wd, 0x00010000u, s2);
                s3 = __dp4a(wd, 0x01000000u, s3);
            }
        }
        atomicAdd(&g_counts[4u * r + 0u], s0);
        atomicAdd(&g_counts[4u * r + 1u], s1);
        atomicAdd(&g_counts[4u * r + 2u], s2);
        atomicAdd(&g_counts[4u * r + 3u], s3);
    }

    // ---- last-block finalize ----------------------------------------------
    __threadfence();
    __shared__ unsigned ticket;
    if (threadIdx.x == 0) ticket = atomicAdd(&g_done, 1u);
    __syncthreads();

    if (ticket == gridDim.x - 1) {
        const unsigned j = threadIdx.x;
        const float inv_temp = 1.0f / 4194304.0f;     // 1/(2048*2048)
        unsigned c0 = __ldcg(&g_counts[j]);
        unsigned c1 = __ldcg(&g_counts[j + 128]);
        double term = 0.0;
        if (c0) { float p = (float)c0 * inv_temp; term += (double)(p * log2f(p)); }
        if (c1) { float p = (float)c1 * inv_temp; term += (double)(p * log2f(p)); }

        #pragma unroll
        for (int o = 16; o > 0; o >>= 1)
            term += __shfl_down_sync(0xffffffffu, term, o);

        __shared__ double sred[4];
        if ((j & 31u) == 0u) sred[j >> 5] = term;
        __syncthreads();
        if (j == 0) {
            double s = sred[0] + sred[1] + sred[2] + sred[3];
            float B = (float)(n >> 22);               // n / (2048*2048)
            out[0] = (float)((double)B * (8.0 + s));
        }
        __syncthreads();
        // reset globals for the next graph replay
        g_counts[j] = 0u;
        g_counts[j + 128] = 0u;
        if (j == 0) g_done = 0u;
    }
}

extern "C" void kernel_launch(void* const* d_in, const int* in_sizes, int n_in,
                              void* d_out, int out_size) {
    const float* img = (const float*)d_in[0];
    int n = in_sizes[0];
    cudaFuncSetAttribute(de3_fused,
                         cudaFuncAttributeMaxDynamicSharedMemorySize, SMEM_BYTES);
    cudaFuncSetAttribute(de3_fused,
                         cudaFuncAttributePreferredSharedMemoryCarveout, 100);
    de3_fused<<<BLOCKS, THREADS, SMEM_BYTES>>>(
        (const float4*)img, n >> 2, img, n, (float*)d_out);
}

// round 6
// speedup vs baseline: 1.3123x; 1.3123x over previous
#include <cuda_runtime.h>
#include <math.h>

// ---------------------------------------------------------------------------
// DE3 fused: 256-bin histogram entropy, single kernel.
//   out = B * (8 + sum_i p_i log2 p_i),  p_i = counts[i] / (2048*2048)
//
// Unified model from R1-R5: dur == bytes / DRAM-rate; DRAM-rate is set by
// in-flight LDG bytes; in-flight bytes need live REGISTERS for the prefetch
// buffers. R5 failed because __launch_bounds__(...,7) capped regs at 64 and
// ptxas serialized the pipeline (regs=55, same 1.0 TB/s as R3).
//
// This round: u8 conflict-free per-thread histograms (32 KB/block, bank==lane
// for every access) + DEPTH=6 pipeline + __launch_bounds__(128, 5):
//   reg cap 102 (fits ~75 needed), 5 blocks/SM = 20 warps/SM,
//   in-flight = 20 warps * 6 LDG.128 * 512 B ~= 61 KB/SM  (R4: 49 KB).
//
//   counter(thread, bin) at byte  warp*8192 + (bin>>2)*128 + lane*4 + (bin&3)
//                               = bin*32 + base - (bin&3)*31
// Grid 2220 = 148*5*3 (3 waves): <=240 elements/thread -> u8 safe (<255).
// ---------------------------------------------------------------------------

#define NUM_BINS 256
#define THREADS  128
#define BLOCKS   2220
#define SMEM_BYTES 32768      // 4 warps * 8192 B
#define DEPTH    6

__device__ unsigned int g_counts[NUM_BINS];   // zero-init at load
__device__ unsigned int g_done;

__global__ void __launch_bounds__(THREADS, 5)
de3_fused(const float4* __restrict__ in4, int n4,
          const float* __restrict__ in, int n,
          float* __restrict__ out)
{
    extern __shared__ unsigned char smem[];

    // zero private histograms: 2048 uint4 / 128 threads = 16 STS.128 each
    {
        uint4* z = reinterpret_cast<uint4*>(smem);
        #pragma unroll
        for (int i = threadIdx.x; i < SMEM_BYTES / 16; i += THREADS)
            z[i] = make_uint4(0u, 0u, 0u, 0u);
    }
    __syncthreads();

    const unsigned lane = threadIdx.x & 31u;
    const unsigned warp = threadIdx.x >> 5;
    const unsigned base = (warp << 13) + (lane << 2);   // warp*8192 + lane*4

    // bump: FMNMX, F2I, AND, IMAD, IMAD, LDS.U8, IADD, STS.U8 — conflict-free
    #define DE3_BUMP(V) do {                                           \
        unsigned b_  = __float2uint_rz(fminf((V), 255.0f));            \
        unsigned lo_ = b_ & 3u;                                        \
        unsigned a_  = b_ * 32u + base - lo_ * 31u;                    \
        smem[a_] = (unsigned char)(smem[a_] + 1u);                     \
    } while (0)
    #define DE3_BUMP4(Q) do { DE3_BUMP((Q).x); DE3_BUMP((Q).y);       \
                              DE3_BUMP((Q).z); DE3_BUMP((Q).w); } while (0)

    const int S  = BLOCKS * THREADS;     // 284160
    const int SD = DEPTH * S;
    int i = blockIdx.x * THREADS + threadIdx.x;

    // ---- DEPTH-deep software pipeline: next batch's LDG.128s issue BEFORE
    //      the current batch's smem work (keeps DEPTH loads in flight).
    if (i + (DEPTH - 1) * S < n4) {
        float4 buf[DEPTH];
        #pragma unroll
        for (int k = 0; k < DEPTH; ++k) buf[k] = __ldcs(in4 + i + k * S);
        i += SD;
        while (i + (DEPTH - 1) * S < n4) {
            float4 nxt[DEPTH];
            #pragma unroll
            for (int k = 0; k < DEPTH; ++k) nxt[k] = __ldcs(in4 + i + k * S);
            #pragma unroll
            for (int k = 0; k < DEPTH; ++k) DE3_BUMP4(buf[k]);
            #pragma unroll
            for (int k = 0; k < DEPTH; ++k) buf[k] = nxt[k];
            i += SD;
        }
        #pragma unroll
        for (int k = 0; k < DEPTH; ++k) DE3_BUMP4(buf[k]);
    }
    for (; i < n4; i += S) {
        float4 a = __ldcs(in4 + i);
        DE3_BUMP4(a);
    }
    if (blockIdx.x == 0 && (int)threadIdx.x < (n & 3)) {
        float v = in[(n & ~3) + (int)threadIdx.x];
        DE3_BUMP(v);
    }
    #undef DE3_BUMP4
    #undef DE3_BUMP
    __syncthreads();

    // ---- block reduction (proven in R3/R5) --------------------------------
    // Word (warp w, row r, lane l) at word-index w*2048 + r*32 + l holds the
    // u8 counters of bins 4r..4r+3 for thread (w,l). dp4a byte-lane sums.
    {
        const unsigned* w32 = reinterpret_cast<const unsigned*>(smem);
        const unsigned j = threadIdx.x;
        const unsigned r = j & 63u;
        const unsigned wp0 = (j >> 6) << 1;
        unsigned s0 = 0u, s1 = 0u, s2 = 0u, s3 = 0u;
        #pragma unroll
        for (unsigned w = 0; w < 2; ++w) {
            const unsigned rowbase = (wp0 + w) * 2048u + r * 32u;
            #pragma unroll
            for (unsigned k = 0; k < 32; ++k) {
                unsigned l = (k + j) & 31u;
                unsigned wd = w32[rowbase + l];
                s0 = __dp4a(wd, 0x00000001u, s0);
                s1 = __dp4a(wd, 0x00000100u, s1);
                s2 = __dp4a(wd, 0x00010000u, s2);
                s3 = __dp4a(wd, 0x01000000u, s3);
            }
        }
        atomicAdd(&g_counts[4u * r + 0u], s0);
        atomicAdd(&g_counts[4u * r + 1u], s1);
        atomicAdd(&g_counts[4u * r + 2u], s2);
        atomicAdd(&g_counts[4u * r + 3u], s3);
    }

    // ---- last-block finalize ----------------------------------------------
    __threadfence();
    __shared__ unsigned ticket;
    if (threadIdx.x == 0) ticket = atomicAdd(&g_done, 1u);
    __syncthreads();

    if (ticket == gridDim.x - 1) {
        const unsigned j = threadIdx.x;
        const float inv_temp = 1.0f / 4194304.0f;     // 1/(2048*2048)
        unsigned c0 = __ldcg(&g_counts[j]);
        unsigned c1 = __ldcg(&g_counts[j + 128]);
        double term = 0.0;
        if (c0) { float p = (float)c0 * inv_temp; term += (double)(p * log2f(p)); }
        if (c1) { float p = (float)c1 * inv_temp; term += (double)(p * log2f(p)); }

        #pragma unroll
        for (int o = 16; o > 0; o >>= 1)
            term += __shfl_down_sync(0xffffffffu, term, o);

        __shared__ double sred[4];
        if ((j & 31u) == 0u) sred[j >> 5] = term;
        __syncthreads();
        if (j == 0) {
            double s = sred[0] + sred[1] + sred[2] + sred[3];
            float B = (float)(n >> 22);               // n / (2048*2048)
            out[0] = (float)((double)B * (8.0 + s));
        }
        __syncthreads();
        // reset globals for the next graph replay
        g_counts[j] = 0u;
        g_counts[j + 128] = 0u;
        if (j == 0) g_done = 0u;
    }
}

extern "C" void kernel_launch(void* const* d_in, const int* in_sizes, int n_in,
                              void* d_out, int out_size) {
    const float* img = (const float*)d_in[0];
    int n = in_sizes[0];
    cudaFuncSetAttribute(de3_fused,
                         cudaFuncAttributeMaxDynamicSharedMemorySize, SMEM_BYTES);
    cudaFuncSetAttribute(de3_fused,
                         cudaFuncAttributePreferredSharedMemoryCarveout, 100);
    de3_fused<<<BLOCKS, THREADS, SMEM_BYTES>>>(
        (const float4*)img, n >> 2, img, n, (float*)d_out);
}

// round 7
// speedup vs baseline: 4.6466x; 3.5407x over previous
#include <cuda_runtime.h>
#include <math.h>

// ---------------------------------------------------------------------------
// DE3 fused: 256-bin histogram entropy, single kernel.
//   out = B * (8 + sum_i p_i log2 p_i),  p_i = counts[i] / (2048*2048)
//
// Exactly the proven R4 structure (59.8us, regs=97, 4.65 TB/s) with the
// prefetch pipeline deepened 8 -> 12. Evidence: u8-layout builds are
// consistently de-pipelined by ptxas (regs 55-63 at any cap); the u16 loop
// shape is the one ptxas keeps live. DEPTH=12 raises in-flight bytes/SM
// from 49 KB to 74 KB at ~constant per-iteration latency cost.
//
// Per-THREAD private u16 histograms in smem:
//   counter(thread, bin) at byte  warp*16384 + bin*64 + lane*2
//   -> 1 IMAD address; lanes 2k/2k+1 share a word, worst conflict 2-way.
// Grid = 444 blocks x 128 thr (3 blocks/SM, 64KB smem, one wave).
// Max elements/thread = 1184 < 65535: no u16 overflow.
// ---------------------------------------------------------------------------

#define NUM_BINS 256
#define THREADS  128
#define BLOCKS   444
#define SMEM_BYTES 65536   // 4 warps * 256 bins * 64 B
#define DEPTH    12

__device__ unsigned int g_counts[NUM_BINS];   // zero-initialized at load
__device__ unsigned int g_done;

__global__ void __launch_bounds__(THREADS, 3)
de3_fused(const float4* __restrict__ in4, int n4,
          const float* __restrict__ in, int n,
          float* __restrict__ out)
{
    extern __shared__ unsigned char smem[];

    // zero private histograms
    {
        uint4* z = reinterpret_cast<uint4*>(smem);
        #pragma unroll
        for (int i = threadIdx.x; i < SMEM_BYTES / 16; i += THREADS)
            z[i] = make_uint4(0u, 0u, 0u, 0u);
    }
    __syncthreads();

    const unsigned lane = threadIdx.x & 31u;
    const unsigned warp = threadIdx.x >> 5;
    const unsigned lanebase = (warp << 14) + (lane << 1);  // warp*16KB + lane*2

    #define DE3_BUMP(V) do {                                                  \
        unsigned b_ = __float2uint_rz(fminf((V), 255.0f));                    \
        unsigned short* c_ =                                                  \
            reinterpret_cast<unsigned short*>(smem + (b_ * 64u + lanebase));  \
        *c_ = (unsigned short)(*c_ + 1u);                                     \
    } while (0)
    #define DE3_BUMP4(Q) do { DE3_BUMP((Q).x); DE3_BUMP((Q).y);              \
                              DE3_BUMP((Q).z); DE3_BUMP((Q).w); } while (0)

    const int S  = BLOCKS * THREADS;       // 56832
    const int SD = DEPTH * S;
    int i = blockIdx.x * THREADS + threadIdx.x;

    // ---- DEPTH-deep software pipeline: next batch's LDG.128s issue BEFORE
    //      the current batch's smem work (keeps DEPTH loads in flight/thread).
    if (i + (DEPTH - 1) * S < n4) {
        float4 buf[DEPTH];
        #pragma unroll
        for (int k = 0; k < DEPTH; ++k) buf[k] = __ldcs(in4 + i + k * S);
        i += SD;
        while (i + (DEPTH - 1) * S < n4) {
            float4 nxt[DEPTH];
            #pragma unroll
            for (int k = 0; k < DEPTH; ++k) nxt[k] = __ldcs(in4 + i + k * S);
            #pragma unroll
            for (int k = 0; k < DEPTH; ++k) DE3_BUMP4(buf[k]);
            #pragma unroll
            for (int k = 0; k < DEPTH; ++k) buf[k] = nxt[k];
            i += SD;
        }
        #pragma unroll
        for (int k = 0; k < DEPTH; ++k) DE3_BUMP4(buf[k]);
    }
    // tail: remaining strided singles
    for (; i < n4; i += S) {
        float4 a = __ldcs(in4 + i);
        DE3_BUMP4(a);
    }
    // scalar tail (n % 4), block 0 (empty for n = 2^26)
    if (blockIdx.x == 0 && (int)threadIdx.x < (n & 3)) {
        float v = in[(n & ~3) + (int)threadIdx.x];
        DE3_BUMP(v);
    }
    #undef DE3_BUMP4
    #undef DE3_BUMP
    __syncthreads();

    // ---- block reduction: thread j sums bins j and j+128 -------------------
    // Packed-u16 SIMD adds (16*1184 < 65536: no carry), staggered banks.
    const unsigned j = threadIdx.x;
    unsigned tot0 = 0u, tot1 = 0u;
    #pragma unroll
    for (int w = 0; w < 4; ++w) {
        const unsigned base0 = ((unsigned)w << 14) + j * 64u;
        const unsigned base1 = ((unsigned)w << 14) + (j + 128u) * 64u;
        unsigned acc0 = 0u, acc1 = 0u;
        #pragma unroll
        for (unsigned s = 0; s < 16; ++s) {
            unsigned k = (((j >> 1) + s) & 15u) << 2;
            acc0 += *reinterpret_cast<const unsigned*>(smem + base0 + k);
            acc1 += *reinterpret_cast<const unsigned*>(smem + base1 + k);
        }
        tot0 += (acc0 & 0xFFFFu) + (acc0 >> 16);
        tot1 += (acc1 & 0xFFFFu) + (acc1 >> 16);
    }
    atomicAdd(&g_counts[j],       tot0);
    atomicAdd(&g_counts[j + 128], tot1);

    // ---- last-block finalize ----------------------------------------------
    __threadfence();
    __shared__ unsigned ticket;
    if (threadIdx.x == 0) ticket = atomicAdd(&g_done, 1u);
    __syncthreads();

    if (ticket == gridDim.x - 1) {
        const float inv_temp = 1.0f / 4194304.0f;   // 1/(2048*2048)
        unsigned c0 = __ldcg(&g_counts[j]);
        unsigned c1 = __ldcg(&g_counts[j + 128]);
        double term = 0.0;
        if (c0) { float p = (float)c0 * inv_temp; term += (double)(p * log2f(p)); }
        if (c1) { float p = (float)c1 * inv_temp; term += (double)(p * log2f(p)); }

        #pragma unroll
        for (int o = 16; o > 0; o >>= 1)
            term += __shfl_down_sync(0xffffffffu, term, o);

        __shared__ double sred[4];
        if ((j & 31u) == 0u) sred[j >> 5] = term;
        __syncthreads();
        if (j == 0) {
            double s = sred[0] + sred[1] + sred[2] + sred[3];
            float B = (float)(n >> 22);              // n / (2048*2048)
            out[0] = (float)((double)B * (8.0 + s));
        }
        __syncthreads();
        // reset device globals for the next graph replay
        g_counts[j] = 0u;
        g_counts[j + 128] = 0u;
        if (j == 0) g_done = 0u;
    }
}

extern "C" void kernel_launch(void* const* d_in, const int* in_sizes, int n_in,
                              void* d_out, int out_size) {
    const float* img = (const float*)d_in[0];
    int n = in_sizes[0];
    cudaFuncSetAttribute(de3_fused,
                         cudaFuncAttributeMaxDynamicSharedMemorySize, SMEM_BYTES);
    de3_fused<<<BLOCKS, THREADS, SMEM_BYTES>>>(
        (const float4*)img, n >> 2, img, n, (float*)d_out);
}